// round 13
// baseline (speedup 1.0000x reference)
#include <cuda_runtime.h>
#include <stdint.h>

#define D_EMB   512
#define H_NUM   8
#define T_STEPS 16
#define NB      2
#define SEQ     512
#define HD      64
#define M_ROWS  (NB * T_STEPS * SEQ)      // 16384
#define PBATCH  (NB * T_STEPS * H_NUM)    // 256

// ---- scratch ----
__device__ float g_Q[(size_t)M_ROWS * D_EMB];
__device__ float g_K[(size_t)M_ROWS * D_EMB];
__device__ float g_V[(size_t)M_ROWS * D_EMB];
__device__ float g_att[(size_t)M_ROWS * D_EMB];

// ---- helpers ----
__device__ __forceinline__ uint32_t f2tf(float x) {
    uint32_t r;
    asm("cvt.rna.tf32.f32 %0, %1;" : "=r"(r) : "f"(x));
    return r;
}
__device__ __forceinline__ void mma8(float* c, const uint32_t* a, uint32_t b0, uint32_t b1) {
    asm volatile(
        "mma.sync.aligned.m16n8k8.row.col.f32.tf32.tf32.f32 "
        "{%0,%1,%2,%3}, {%4,%5,%6,%7}, {%8,%9}, {%0,%1,%2,%3};"
        : "+f"(c[0]), "+f"(c[1]), "+f"(c[2]), "+f"(c[3])
        : "r"(a[0]), "r"(a[1]), "r"(a[2]), "r"(a[3]), "r"(b0), "r"(b1));
}
__device__ __forceinline__ void cpa16(uint32_t dst, const void* src) {
    asm volatile("cp.async.ca.shared.global [%0], [%1], 16;" :: "r"(dst), "l"(src));
}
__device__ __forceinline__ void cpa_commit() { asm volatile("cp.async.commit_group;"); }
__device__ __forceinline__ void cpa_wait1() { asm volatile("cp.async.wait_group 1;"); }
__device__ __forceinline__ void cpa_wait0() { asm volatile("cp.async.wait_group 0;"); }

// ============================================================================
// merged projection GEMM: z selects (A, W, bias, C) triple.
// Per stage: cp.async raw tiles -> in-smem tf32 convert (A in place; W
// pair-interleaved into Wi so each mma8 B-operand is one LDS.64, zero cvt
// in the MMA loop). roundC!=0: round outputs to tf32 for fused_attn.
// smem: A [2][128][36] + Wraw [2][32][136] + Wi [16][272] = 89088 B.
// ============================================================================
#define PJ_AS_W 4608          // 128*36
#define PJ_WR_W 4352          // 32*136
#define PJ_WI_W 4352          // 16*272
#define PJ_SMEM 89088
__global__ __launch_bounds__(256, 2) void proj3_gemm(
    const float* __restrict__ A0, const float* __restrict__ W0,
    const float* __restrict__ B0, float* __restrict__ C0,
    const float* __restrict__ A1, const float* __restrict__ W1,
    const float* __restrict__ B1, float* __restrict__ C1,
    const float* __restrict__ A2, const float* __restrict__ W2,
    const float* __restrict__ B2, float* __restrict__ C2,
    int roundC)
{
    const int z = blockIdx.z;
    const float* A    = (z == 0) ? A0 : (z == 1) ? A1 : A2;
    const float* W    = (z == 0) ? W0 : (z == 1) ? W1 : W2;
    const float* bias = (z == 0) ? B0 : (z == 1) ? B1 : B2;
    float*       C    = (z == 0) ? C0 : (z == 1) ? C1 : C2;

    extern __shared__ __align__(16) unsigned char smraw[];
    float*    As = (float*)smraw;                              // [2][128][36]
    float*    Wr = (float*)(smraw + 2 * PJ_AS_W * 4);          // [2][32][136]
    uint32_t* Wi = (uint32_t*)(smraw + 2 * PJ_AS_W * 4 + 2 * PJ_WR_W * 4); // [16][272]
    const uint32_t sAs = (uint32_t)__cvta_generic_to_shared(As);
    const uint32_t sWr = (uint32_t)__cvta_generic_to_shared(Wr);

    const int tid = threadIdx.x;
    const int lane = tid & 31, warp = tid >> 5;
    const int g = lane >> 2, t = lane & 3;
    const int wm = (warp >> 1) * 32;
    const int wn = (warp & 1) * 64;
    const int rowBlk = blockIdx.y * 128;
    const int colBlk = blockIdx.x * 128;

    auto issue = [&](int st) {
        const int buf = st & 1;
        const int k0 = st * 32;
#pragma unroll
        for (int i = 0; i < 4; i++) {
            int seg = i * 256 + tid;
            int r = seg >> 3, s = (seg & 7) << 2;
            cpa16(sAs + ((buf * PJ_AS_W + r * 36 + s) << 2),
                  A + (size_t)(rowBlk + r) * 512 + k0 + s);
        }
#pragma unroll
        for (int i = 0; i < 4; i++) {
            int seg = i * 256 + tid;
            int kr = seg >> 5, s = (seg & 31) << 2;
            cpa16(sWr + ((buf * PJ_WR_W + kr * 136 + s) << 2),
                  W + (size_t)(k0 + kr) * 512 + colBlk + s);
        }
        cpa_commit();
    };

    float acc[2][8][4] = {};
    issue(0);
    for (int st = 0; st < 16; st++) {
        if (st + 1 < 16) { issue(st + 1); cpa_wait1(); } else cpa_wait0();
        __syncthreads();
        float*       Ab = As + (st & 1) * PJ_AS_W;
        const float* Wb = Wr + (st & 1) * PJ_WR_W;

        // ---- convert: A in place; W pair-interleaved (k, k+4) into Wi ----
        {
            const int r = tid >> 1, c0 = (tid & 1) * 16;
            uint32_t* Aw = (uint32_t*)Ab;
#pragma unroll
            for (int j = 0; j < 4; j++) {
                float4 v = *(float4*)(Ab + r * 36 + c0 + j * 4);
                uint4 u = {f2tf(v.x), f2tf(v.y), f2tf(v.z), f2tf(v.w)};
                *(uint4*)(Aw + r * 36 + c0 + j * 4) = u;
            }
#pragma unroll
            for (int i = 0; i < 8; i++) {
                int pid = i * 256 + tid;
                int k2l = pid >> 7, n = pid & 127;
                int k = ((k2l >> 2) << 3) + (k2l & 3);
                uint2 u2;
                u2.x = f2tf(Wb[k * 136 + n]);
                u2.y = f2tf(Wb[(k + 4) * 136 + n]);
                *(uint2*)(Wi + k2l * 272 + 2 * n) = u2;
            }
        }
        __syncthreads();

        // ---- MMA loop: zero cvt; B operand = one LDS.64 pair ----
        const uint32_t* Au = (const uint32_t*)Ab;
#pragma unroll
        for (int ks = 0; ks < 4; ks++) {
            const int kc = ks * 8 + t;
            const int k2l = ks * 4 + t;
            uint32_t a[2][4];
#pragma unroll
            for (int mi = 0; mi < 2; mi++) {
                const int m = wm + mi * 16 + g;
                a[mi][0] = Au[m * 36 + kc];
                a[mi][1] = Au[(m + 8) * 36 + kc];
                a[mi][2] = Au[m * 36 + kc + 4];
                a[mi][3] = Au[(m + 8) * 36 + kc + 4];
            }
#pragma unroll
            for (int ni = 0; ni < 8; ni++) {
                const int n = wn + ni * 8 + g;
                uint2 bv = *(const uint2*)(Wi + k2l * 272 + n * 2);
                mma8(acc[0][ni], a[0], bv.x, bv.y);
                mma8(acc[1][ni], a[1], bv.x, bv.y);
            }
        }
        __syncthreads();
    }
#pragma unroll
    for (int mi = 0; mi < 2; mi++)
#pragma unroll
        for (int ni = 0; ni < 8; ni++) {
            const int col = colBlk + wn + ni * 8 + 2 * t;
            const float bx = bias[col], by = bias[col + 1];
            const int r0 = rowBlk + wm + mi * 16 + g;
            float2 v0 = {acc[mi][ni][0] + bx, acc[mi][ni][1] + by};
            float2 v1 = {acc[mi][ni][2] + bx, acc[mi][ni][3] + by};
            if (roundC) {
                v0.x = __uint_as_float(f2tf(v0.x)); v0.y = __uint_as_float(f2tf(v0.y));
                v1.x = __uint_as_float(f2tf(v1.x)); v1.y = __uint_as_float(f2tf(v1.y));
            }
            *(float2*)(C + (size_t)r0 * 512 + col) = v0;
            *(float2*)(C + (size_t)(r0 + 8) * 512 + col) = v1;
        }
}

// ============================================================================
// fused attention (unchanged from R11): register-resident scores, raw tf32
// operand loads. 512 threads (16 warps, 4Mx4N).
// ============================================================================
#define FA_QK_W  68
#define FA_V_W   72
#define FA_KBUF  (64 * FA_QK_W)
#define FA_VBUF  (64 * FA_V_W)
#define FA_QOFF  0
#define FA_KOFF  17408
#define FA_VOFF  52224
#define FA_STAT  89088
#define FA_SMEM  90112
__global__ __launch_bounds__(512, 1) void fused_attn(
    const float* __restrict__ mw, const float* __restrict__ tsync,
    const int* __restrict__ qm, const int* __restrict__ km)
{
    extern __shared__ __align__(16) unsigned char smraw[];
    uint32_t* Qs    = (uint32_t*)(smraw + FA_QOFF);   // [64][68]
    uint32_t* Ks    = (uint32_t*)(smraw + FA_KOFF);   // [2][64][68]
    uint32_t* Vs    = (uint32_t*)(smraw + FA_VOFF);   // [2][64][72]
    float*    stats = (float*)(smraw + FA_STAT);      // [64][4]
    float*    Opart = (float*)smraw;                  // [16][16][68] overlay
    const uint32_t sQ = (uint32_t)__cvta_generic_to_shared(Qs);
    const uint32_t sK = (uint32_t)__cvta_generic_to_shared(Ks);
    const uint32_t sV = (uint32_t)__cvta_generic_to_shared(Vs);

    const int tid = threadIdx.x;
    const int lane = tid & 31, warp = tid >> 5;
    const int g = lane >> 2, t = lane & 3;
    const int wm = (warp >> 2) * 16;
    const int wni = warp & 3;
    const int wn = wni * 16;
    const int sig = (g >> 1) + ((g & 1) << 2);

    const int tile = blockIdx.x;
    const int p = blockIdx.y;
    const int h = p & 7;
    const int tt = (p >> 3) & 15;
    const int b = p >> 7;
    const size_t rowbase = ((size_t)(b * T_STEPS + tt) * SEQ);
    const float* Qg = g_Q + (rowbase + tile * 64) * 512 + h * HD;
    const float* Kg = g_K + rowbase * 512 + h * HD;
    const float* Vg = g_V + rowbase * 512 + h * HD;
    float*       Cg = g_att + (rowbase + tile * 64) * 512 + h * HD;

    const float alpha = 0.125f * mw[qm[0] * H_NUM + h] * mw[km[0] * H_NUM + h];
    const float sy = tsync[tt * H_NUM + h];

    // ---- prologue: {Q + K0} group, {K1} group ----
#pragma unroll
    for (int i = 0; i < 2; i++) {
        int seg = i * 512 + tid;
        int r = seg >> 4, s = (seg & 15) << 2;
        cpa16(sQ + ((r * FA_QK_W + s) << 2), Qg + (size_t)r * 512 + s);
        cpa16(sK + ((r * FA_QK_W + s) << 2), Kg + (size_t)r * 512 + s);
    }
    cpa_commit();
#pragma unroll
    for (int i = 0; i < 2; i++) {
        int seg = i * 512 + tid;
        int r = seg >> 4, s = (seg & 15) << 2;
        cpa16(sK + ((FA_KBUF + r * FA_QK_W + s) << 2),
              Kg + (size_t)(64 + r) * 512 + s);
    }
    cpa_commit();
    cpa_wait1();
    __syncthreads();

    // ---- preload Q a-fragments (raw: pre-rounded) ----
    uint32_t Qf[8][4];
#pragma unroll
    for (int ks = 0; ks < 8; ks++) {
        const int kc = ks * 8 + t;
        Qf[ks][0] = Qs[(wm + g) * FA_QK_W + kc];
        Qf[ks][1] = Qs[(wm + 8 + g) * FA_QK_W + kc];
        Qf[ks][2] = Qs[(wm + g) * FA_QK_W + kc + 4];
        Qf[ks][3] = Qs[(wm + 8 + g) * FA_QK_W + kc + 4];
    }

    // ---- phase 1: scores into registers ----
    float accS[8][2][4] = {};
#pragma unroll
    for (int c = 0; c < 8; c++) {
        if (c < 7) cpa_wait1(); else cpa_wait0();
        __syncthreads();
        const uint32_t* Kb = Ks + (c & 1) * FA_KBUF;
#pragma unroll
        for (int ks = 0; ks < 8; ks++) {
            const int kc = ks * 8 + t;
#pragma unroll
            for (int kt = 0; kt < 2; kt++) {
                const int n = wn + kt * 8 + sig;
                uint32_t b0 = Kb[n * FA_QK_W + kc];
                uint32_t b1 = Kb[n * FA_QK_W + kc + 4];
                mma8(accS[c][kt], Qf[ks], b0, b1);
            }
        }
        __syncthreads();
        if (c + 2 < 8) {
            const int buf = c & 1;
#pragma unroll
            for (int i = 0; i < 2; i++) {
                int seg = i * 512 + tid;
                int r = seg >> 4, s = (seg & 15) << 2;
                cpa16(sK + ((buf * FA_KBUF + r * FA_QK_W + s) << 2),
                      Kg + (size_t)((c + 2) * 64 + r) * 512 + s);
            }
            cpa_commit();
        }
    }

    // ---- prefetch V chunks 0,1 ----
#pragma unroll
    for (int cc = 0; cc < 2; cc++) {
#pragma unroll
        for (int i = 0; i < 2; i++) {
            int seg = i * 512 + tid;
            int r = seg >> 4, s = (seg & 15) << 2;
            cpa16(sV + ((cc * FA_VBUF + r * FA_V_W + s) << 2),
                  Vg + (size_t)(cc * 64 + r) * 512 + s);
        }
        cpa_commit();
    }

    // ---- register softmax ----
    {
        float* aS = &accS[0][0][0];
#pragma unroll
        for (int i = 0; i < 64; i++) aS[i] = aS[i] * alpha + sy;

        float m0 = -1e30f, m1 = -1e30f;
#pragma unroll
        for (int i = 0; i < 64; i += 4) {
            m0 = fmaxf(m0, fmaxf(aS[i], aS[i + 1]));
            m1 = fmaxf(m1, fmaxf(aS[i + 2], aS[i + 3]));
        }
        m0 = fmaxf(m0, __shfl_xor_sync(0xFFFFFFFFu, m0, 1));
        m0 = fmaxf(m0, __shfl_xor_sync(0xFFFFFFFFu, m0, 2));
        m1 = fmaxf(m1, __shfl_xor_sync(0xFFFFFFFFu, m1, 1));
        m1 = fmaxf(m1, __shfl_xor_sync(0xFFFFFFFFu, m1, 2));
        if (t == 0) {
            stats[(wm + g) * 4 + wni] = m0;
            stats[(wm + 8 + g) * 4 + wni] = m1;
        }
        __syncthreads();
        {
            float4 v0 = *(float4*)&stats[(wm + g) * 4];
            m0 = fmaxf(fmaxf(v0.x, v0.y), fmaxf(v0.z, v0.w));
            float4 v1 = *(float4*)&stats[(wm + 8 + g) * 4];
            m1 = fmaxf(fmaxf(v1.x, v1.y), fmaxf(v1.z, v1.w));
        }
        __syncthreads();

        float s0 = 0.f, s1 = 0.f;
#pragma unroll
        for (int i = 0; i < 64; i += 4) {
            float p0 = 1.f / (1.f + __expf(-5.f * (aS[i]     - m0)));
            float p1 = 1.f / (1.f + __expf(-5.f * (aS[i + 1] - m0)));
            float p2 = 1.f / (1.f + __expf(-5.f * (aS[i + 2] - m1)));
            float p3 = 1.f / (1.f + __expf(-5.f * (aS[i + 3] - m1)));
            aS[i] = p0; aS[i + 1] = p1; aS[i + 2] = p2; aS[i + 3] = p3;
            s0 += p0 + p1; s1 += p2 + p3;
        }
        s0 += __shfl_xor_sync(0xFFFFFFFFu, s0, 1);
        s0 += __shfl_xor_sync(0xFFFFFFFFu, s0, 2);
        s1 += __shfl_xor_sync(0xFFFFFFFFu, s1, 1);
        s1 += __shfl_xor_sync(0xFFFFFFFFu, s1, 2);
        if (t == 0) {
            stats[(wm + g) * 4 + wni] = s0;
            stats[(wm + 8 + g) * 4 + wni] = s1;
        }
        __syncthreads();
        {
            float4 v0 = *(float4*)&stats[(wm + g) * 4];
            s0 = v0.x + v0.y + v0.z + v0.w;
            float4 v1 = *(float4*)&stats[(wm + 8 + g) * 4];
            s1 = v1.x + v1.y + v1.z + v1.w;
        }
        const float inv0 = 1.f / (s0 + 1e-8f);
        const float inv1 = 1.f / (s1 + 1e-8f);
#pragma unroll
        for (int i = 0; i < 64; i += 4) {
            aS[i]     = __uint_as_float(f2tf(aS[i]     * inv0));
            aS[i + 1] = __uint_as_float(f2tf(aS[i + 1] * inv0));
            aS[i + 2] = __uint_as_float(f2tf(aS[i + 2] * inv1));
            aS[i + 3] = __uint_as_float(f2tf(aS[i + 3] * inv1));
        }
    }

    // ---- phase 2: partial O over this warp's 128 keys ----
    float acc2[8][4] = {};
#pragma unroll
    for (int c = 0; c < 8; c++) {
        if (c < 7) cpa_wait1(); else cpa_wait0();
        __syncthreads();
        const uint32_t* Vb = Vs + (c & 1) * FA_VBUF;
#pragma unroll
        for (int kt = 0; kt < 2; kt++) {
            uint32_t a[4];
            a[0] = __float_as_uint(accS[c][kt][0]);
            a[1] = __float_as_uint(accS[c][kt][2]);
            a[2] = __float_as_uint(accS[c][kt][1]);
            a[3] = __float_as_uint(accS[c][kt][3]);
            const int klb = wn + kt * 8 + t;
#pragma unroll
            for (int ci = 0; ci < 8; ci++) {
                const int n = ci * 8 + g;
                uint32_t b0 = Vb[klb * FA_V_W + n];
                uint32_t b1 = Vb[(klb + 4) * FA_V_W + n];
                mma8(acc2[ci], a, b0, b1);
            }
        }
        __syncthreads();
        if (c + 2 < 8) {
            const int buf = c & 1;
#pragma unroll
            for (int i = 0; i < 2; i++) {
                int seg = i * 512 + tid;
                int r = seg >> 4, s = (seg & 15) << 2;
                cpa16(sV + ((buf * FA_VBUF + r * FA_V_W + s) << 2),
                      Vg + (size_t)((c + 2) * 64 + r) * 512 + s);
            }
            cpa_commit();
        }
    }

    // ---- epilogue: store partials, 4-way reduce, STG ----
    {
        const int opb = warp * 1088;
#pragma unroll
        for (int ci = 0; ci < 8; ci++) {
            float2 v0 = {acc2[ci][0], acc2[ci][1]};
            *(float2*)&Opart[opb + g * FA_QK_W + ci * 8 + 2 * t] = v0;
            float2 v1 = {acc2[ci][2], acc2[ci][3]};
            *(float2*)&Opart[opb + (g + 8) * FA_QK_W + ci * 8 + 2 * t] = v1;
        }
    }
    __syncthreads();
    {
        const int rr = tid >> 3;
        const int c8 = (tid & 7) * 8;
        float4 o0 = {0.f, 0.f, 0.f, 0.f}, o1 = {0.f, 0.f, 0.f, 0.f};
#pragma unroll
        for (int wv = 0; wv < 4; wv++) {
            const float* src = Opart + ((rr >> 4) * 4 + wv) * 1088
                             + (rr & 15) * FA_QK_W + c8;
            float4 x0 = *(const float4*)src;
            float4 x1 = *(const float4*)(src + 4);
            o0.x += x0.x; o0.y += x0.y; o0.z += x0.z; o0.w += x0.w;
            o1.x += x1.x; o1.y += x1.y; o1.z += x1.z; o1.w += x1.w;
        }
        *(float4*)(Cg + (size_t)rr * 512 + c8) = o0;
        *(float4*)(Cg + (size_t)rr * 512 + c8 + 4) = o1;
    }
}

// ============================================================================
// launch
// ============================================================================
extern "C" void kernel_launch(void* const* d_in, const int* in_sizes, int n_in,
                              void* d_out, int out_size)
{
    const float* q_sp = (const float*)d_in[0];
    const float* k_sp = (const float*)d_in[1];
    const float* v_sp = (const float*)d_in[2];
    const float* Wq = (const float*)d_in[3];  const float* bq = (const float*)d_in[4];
    const float* Wk = (const float*)d_in[5];  const float* bk = (const float*)d_in[6];
    const float* Wv = (const float*)d_in[7];  const float* bv = (const float*)d_in[8];
    const float* Wo = (const float*)d_in[9];  const float* bo = (const float*)d_in[10];
    const float* mw    = (const float*)d_in[11];
    const float* tsync = (const float*)d_in[12];
    const int* qm = (const int*)d_in[13];
    const int* km = (const int*)d_in[14];
    float* out = (float*)d_out;

    // unconditional (no static guards): idempotent, not stream-ordered
    cudaFuncSetAttribute(proj3_gemm, cudaFuncAttributeMaxDynamicSharedMemorySize, PJ_SMEM);
    cudaFuncSetAttribute(fused_attn, cudaFuncAttributeMaxDynamicSharedMemorySize, FA_SMEM);

    float *dQ, *dK, *dV, *dAtt;
    cudaGetSymbolAddress((void**)&dQ, g_Q);
    cudaGetSymbolAddress((void**)&dK, g_K);
    cudaGetSymbolAddress((void**)&dV, g_V);
    cudaGetSymbolAddress((void**)&dAtt, g_att);

    // Q, K, V projections in one launch (outputs tf32-rounded for fused_attn)
    proj3_gemm<<<dim3(D_EMB / 128, M_ROWS / 128, 3), 256, PJ_SMEM>>>(
        q_sp, Wq, bq, dQ,
        k_sp, Wk, bk, dK,
        v_sp, Wv, bv, dV, 1);

    fused_attn<<<dim3(SEQ / 64, PBATCH), 512, FA_SMEM>>>(mw, tsync, qm, km);

    // output projection (full fp32 output)
    proj3_gemm<<<dim3(D_EMB / 128, M_ROWS / 128, 1), 256, PJ_SMEM>>>(
        dAtt, Wo, bo, out,
        dAtt, Wo, bo, out,
        dAtt, Wo, bo, out, 0);
}

// round 14
// speedup vs baseline: 1.2070x; 1.2070x over previous
#include <cuda_runtime.h>
#include <stdint.h>

#define D_EMB   512
#define H_NUM   8
#define T_STEPS 16
#define NB      2
#define SEQ     512
#define HD      64
#define M_ROWS  (NB * T_STEPS * SEQ)      // 16384
#define PBATCH  (NB * T_STEPS * H_NUM)    // 256

// ---- scratch ----
__device__ float g_Q[(size_t)M_ROWS * D_EMB];
__device__ float g_K[(size_t)M_ROWS * D_EMB];
__device__ float g_V[(size_t)M_ROWS * D_EMB];
__device__ float g_att[(size_t)M_ROWS * D_EMB];

// ---- helpers ----
__device__ __forceinline__ uint32_t f2tf(float x) {
    uint32_t r;
    asm("cvt.rna.tf32.f32 %0, %1;" : "=r"(r) : "f"(x));
    return r;
}
__device__ __forceinline__ void mma8(float* c, const uint32_t* a, uint32_t b0, uint32_t b1) {
    asm volatile(
        "mma.sync.aligned.m16n8k8.row.col.f32.tf32.tf32.f32 "
        "{%0,%1,%2,%3}, {%4,%5,%6,%7}, {%8,%9}, {%0,%1,%2,%3};"
        : "+f"(c[0]), "+f"(c[1]), "+f"(c[2]), "+f"(c[3])
        : "r"(a[0]), "r"(a[1]), "r"(a[2]), "r"(a[3]), "r"(b0), "r"(b1));
}
__device__ __forceinline__ void cpa16(uint32_t dst, const void* src) {
    asm volatile("cp.async.ca.shared.global [%0], [%1], 16;" :: "r"(dst), "l"(src));
}
__device__ __forceinline__ void cpa_commit() { asm volatile("cp.async.commit_group;"); }
__device__ __forceinline__ void cpa_wait1() { asm volatile("cp.async.wait_group 1;"); }
__device__ __forceinline__ void cpa_wait0() { asm volatile("cp.async.wait_group 0;"); }

// ============================================================================
// merged projection GEMM (R11 form, verbatim): z selects (A, W, bias, C).
// roundC!=0: tf32-round outputs (so fused_attn can load raw).
// ============================================================================
#define PJ_AS_W 4608
#define PJ_WS_W 4352
#define PJ_SMEM 71680
__global__ __launch_bounds__(256, 2) void proj3_gemm(
    const float* __restrict__ A0, const float* __restrict__ W0,
    const float* __restrict__ B0, float* __restrict__ C0,
    const float* __restrict__ A1, const float* __restrict__ W1,
    const float* __restrict__ B1, float* __restrict__ C1,
    const float* __restrict__ A2, const float* __restrict__ W2,
    const float* __restrict__ B2, float* __restrict__ C2,
    int roundC)
{
    const int z = blockIdx.z;
    const float* A    = (z == 0) ? A0 : (z == 1) ? A1 : A2;
    const float* W    = (z == 0) ? W0 : (z == 1) ? W1 : W2;
    const float* bias = (z == 0) ? B0 : (z == 1) ? B1 : B2;
    float*       C    = (z == 0) ? C0 : (z == 1) ? C1 : C2;

    extern __shared__ __align__(16) unsigned char smraw[];
    float* As = (float*)smraw;
    float* Ws = (float*)(smraw + 2 * PJ_AS_W * 4);
    const uint32_t sAs = (uint32_t)__cvta_generic_to_shared(As);
    const uint32_t sWs = (uint32_t)__cvta_generic_to_shared(Ws);

    const int tid = threadIdx.x;
    const int lane = tid & 31, warp = tid >> 5;
    const int g = lane >> 2, t = lane & 3;
    const int wm = (warp >> 1) * 32;
    const int wn = (warp & 1) * 64;
    const int rowBlk = blockIdx.y * 128;
    const int colBlk = blockIdx.x * 128;

    auto issue = [&](int st) {
        const int buf = st & 1;
        const int k0 = st * 32;
#pragma unroll
        for (int i = 0; i < 4; i++) {
            int seg = i * 256 + tid;
            int r = seg >> 3, s = (seg & 7) << 2;
            cpa16(sAs + ((buf * PJ_AS_W + r * 36 + s) << 2),
                  A + (size_t)(rowBlk + r) * 512 + k0 + s);
        }
#pragma unroll
        for (int i = 0; i < 4; i++) {
            int seg = i * 256 + tid;
            int kr = seg >> 5, s = (seg & 31) << 2;
            cpa16(sWs + ((buf * PJ_WS_W + kr * 136 + s) << 2),
                  W + (size_t)(k0 + kr) * 512 + colBlk + s);
        }
        cpa_commit();
    };

    float acc[2][8][4] = {};
    issue(0);
    for (int st = 0; st < 16; st++) {
        if (st + 1 < 16) { issue(st + 1); cpa_wait1(); } else cpa_wait0();
        __syncthreads();
        const float* Ab = As + (st & 1) * PJ_AS_W;
        const float* Wb = Ws + (st & 1) * PJ_WS_W;
#pragma unroll
        for (int ks = 0; ks < 4; ks++) {
            const int kc = ks * 8 + t;
            uint32_t a[2][4];
#pragma unroll
            for (int mi = 0; mi < 2; mi++) {
                const int m = wm + mi * 16 + g;
                a[mi][0] = f2tf(Ab[m * 36 + kc]);
                a[mi][1] = f2tf(Ab[(m + 8) * 36 + kc]);
                a[mi][2] = f2tf(Ab[m * 36 + kc + 4]);
                a[mi][3] = f2tf(Ab[(m + 8) * 36 + kc + 4]);
            }
#pragma unroll
            for (int ni = 0; ni < 8; ni++) {
                const int n = wn + ni * 8 + g;
                uint32_t b0 = f2tf(Wb[kc * 136 + n]);
                uint32_t b1 = f2tf(Wb[(kc + 4) * 136 + n]);
                mma8(acc[0][ni], a[0], b0, b1);
                mma8(acc[1][ni], a[1], b0, b1);
            }
        }
        __syncthreads();
    }
#pragma unroll
    for (int mi = 0; mi < 2; mi++)
#pragma unroll
        for (int ni = 0; ni < 8; ni++) {
            const int col = colBlk + wn + ni * 8 + 2 * t;
            const float bx = bias[col], by = bias[col + 1];
            const int r0 = rowBlk + wm + mi * 16 + g;
            float2 v0 = {acc[mi][ni][0] + bx, acc[mi][ni][1] + by};
            float2 v1 = {acc[mi][ni][2] + bx, acc[mi][ni][3] + by};
            if (roundC) {
                v0.x = __uint_as_float(f2tf(v0.x)); v0.y = __uint_as_float(f2tf(v0.y));
                v1.x = __uint_as_float(f2tf(v1.x)); v1.y = __uint_as_float(f2tf(v1.y));
            }
            *(float2*)(C + (size_t)r0 * 512 + col) = v0;
            *(float2*)(C + (size_t)(r0 + 8) * 512 + col) = v1;
        }
}

// ============================================================================
// fused attention: register-resident scores, raw tf32 operand loads, and
// 3-stage K/V rotation with ONE barrier per chunk:
//   wait(c) -> sync -> issue c+2 into stage (c+2)%3 -> compute stage c%3.
// The sync both publishes chunk c and retires reads of the refill target
// (which held chunk c-1). smem: Q[64][68] + K 3x[64][68] + V 3x[64][72] +
// stats = 125952 B; Opart[16][16][68] overlays the dead Q+K region.
// grid = (8 qtiles, 256 p), block = 512.
// ============================================================================
#define FA_QK_W  68
#define FA_V_W   72
#define FA_KBUF  (64 * FA_QK_W)    // 4352 words
#define FA_VBUF  (64 * FA_V_W)     // 4608 words
#define FA_QOFF  0
#define FA_KOFF  17408
#define FA_VOFF  69632             // FA_KOFF + 3*4352*4
#define FA_STAT  124928            // FA_VOFF + 3*4608*4
#define FA_SMEM  125952
__global__ __launch_bounds__(512, 1) void fused_attn(
    const float* __restrict__ mw, const float* __restrict__ tsync,
    const int* __restrict__ qm, const int* __restrict__ km)
{
    extern __shared__ __align__(16) unsigned char smraw[];
    uint32_t* Qs    = (uint32_t*)(smraw + FA_QOFF);   // [64][68]
    uint32_t* Ks    = (uint32_t*)(smraw + FA_KOFF);   // [3][64][68]
    uint32_t* Vs    = (uint32_t*)(smraw + FA_VOFF);   // [3][64][72]
    float*    stats = (float*)(smraw + FA_STAT);      // [64][4]
    float*    Opart = (float*)smraw;                  // [16][16][68] overlay
    const uint32_t sQ = (uint32_t)__cvta_generic_to_shared(Qs);
    const uint32_t sK = (uint32_t)__cvta_generic_to_shared(Ks);
    const uint32_t sV = (uint32_t)__cvta_generic_to_shared(Vs);

    const int tid = threadIdx.x;
    const int lane = tid & 31, warp = tid >> 5;
    const int g = lane >> 2, t = lane & 3;
    const int wm = (warp >> 2) * 16;
    const int wni = warp & 3;
    const int wn = wni * 16;
    const int sig = (g >> 1) + ((g & 1) << 2);

    const int tile = blockIdx.x;
    const int p = blockIdx.y;
    const int h = p & 7;
    const int tt = (p >> 3) & 15;
    const int b = p >> 7;
    const size_t rowbase = ((size_t)(b * T_STEPS + tt) * SEQ);
    const float* Qg = g_Q + (rowbase + tile * 64) * 512 + h * HD;
    const float* Kg = g_K + rowbase * 512 + h * HD;
    const float* Vg = g_V + rowbase * 512 + h * HD;
    float*       Cg = g_att + (rowbase + tile * 64) * 512 + h * HD;

    const float alpha = 0.125f * mw[qm[0] * H_NUM + h] * mw[km[0] * H_NUM + h];
    const float sy = tsync[tt * H_NUM + h];

    // chunk-issue helpers (one commit group each)
    auto issueK = [&](int ci, int stage) {
#pragma unroll
        for (int i = 0; i < 2; i++) {
            int seg = i * 512 + tid;
            int r = seg >> 4, s4 = (seg & 15) << 2;
            cpa16(sK + ((stage * FA_KBUF + r * FA_QK_W + s4) << 2),
                  Kg + (size_t)(ci * 64 + r) * 512 + s4);
        }
        cpa_commit();
    };
    auto issueV = [&](int ci, int stage) {
#pragma unroll
        for (int i = 0; i < 2; i++) {
            int seg = i * 512 + tid;
            int r = seg >> 4, s4 = (seg & 15) << 2;
            cpa16(sV + ((stage * FA_VBUF + r * FA_V_W + s4) << 2),
                  Vg + (size_t)(ci * 64 + r) * 512 + s4);
        }
        cpa_commit();
    };

    // ---- prologue: {Q + K0} group, {K1} group ----
#pragma unroll
    for (int i = 0; i < 2; i++) {
        int seg = i * 512 + tid;
        int r = seg >> 4, s4 = (seg & 15) << 2;
        cpa16(sQ + ((r * FA_QK_W + s4) << 2), Qg + (size_t)r * 512 + s4);
        cpa16(sK + ((r * FA_QK_W + s4) << 2), Kg + (size_t)r * 512 + s4);
    }
    cpa_commit();
    issueK(1, 1);
    cpa_wait1();                 // Q + K0 landed
    __syncthreads();

    // ---- preload Q a-fragments (raw: pre-rounded) ----
    uint32_t Qf[8][4];
#pragma unroll
    for (int ks = 0; ks < 8; ks++) {
        const int kc = ks * 8 + t;
        Qf[ks][0] = Qs[(wm + g) * FA_QK_W + kc];
        Qf[ks][1] = Qs[(wm + 8 + g) * FA_QK_W + kc];
        Qf[ks][2] = Qs[(wm + g) * FA_QK_W + kc + 4];
        Qf[ks][3] = Qs[(wm + 8 + g) * FA_QK_W + kc + 4];
    }

    // ---- phase 1: scores into registers (3-stage, 1 barrier/chunk) ----
    float accS[8][2][4] = {};
#pragma unroll
    for (int c = 0; c < 8; c++) {
        if (c < 7) cpa_wait1(); else cpa_wait0();   // chunk c landed
        __syncthreads();                            // publish c; retire stage (c+2)%3 reads
        if (c + 2 < 8) issueK(c + 2, (c + 2) % 3);
        const uint32_t* Kb = Ks + (c % 3) * FA_KBUF;
#pragma unroll
        for (int ks = 0; ks < 8; ks++) {
            const int kc = ks * 8 + t;
#pragma unroll
            for (int kt = 0; kt < 2; kt++) {
                const int n = wn + kt * 8 + sig;
                uint32_t b0 = Kb[n * FA_QK_W + kc];
                uint32_t b1 = Kb[n * FA_QK_W + kc + 4];
                mma8(accS[c][kt], Qf[ks], b0, b1);
            }
        }
    }

    // ---- prefetch V chunks 0,1 (K groups fully drained by wait0) ----
    issueV(0, 0);
    issueV(1, 1);

    // ---- register softmax ----
    {
        float* aS = &accS[0][0][0];
#pragma unroll
        for (int i = 0; i < 64; i++) aS[i] = aS[i] * alpha + sy;

        float m0 = -1e30f, m1 = -1e30f;
#pragma unroll
        for (int i = 0; i < 64; i += 4) {
            m0 = fmaxf(m0, fmaxf(aS[i], aS[i + 1]));
            m1 = fmaxf(m1, fmaxf(aS[i + 2], aS[i + 3]));
        }
        m0 = fmaxf(m0, __shfl_xor_sync(0xFFFFFFFFu, m0, 1));
        m0 = fmaxf(m0, __shfl_xor_sync(0xFFFFFFFFu, m0, 2));
        m1 = fmaxf(m1, __shfl_xor_sync(0xFFFFFFFFu, m1, 1));
        m1 = fmaxf(m1, __shfl_xor_sync(0xFFFFFFFFu, m1, 2));
        if (t == 0) {
            stats[(wm + g) * 4 + wni] = m0;
            stats[(wm + 8 + g) * 4 + wni] = m1;
        }
        __syncthreads();
        {
            float4 v0 = *(float4*)&stats[(wm + g) * 4];
            m0 = fmaxf(fmaxf(v0.x, v0.y), fmaxf(v0.z, v0.w));
            float4 v1 = *(float4*)&stats[(wm + 8 + g) * 4];
            m1 = fmaxf(fmaxf(v1.x, v1.y), fmaxf(v1.z, v1.w));
        }
        __syncthreads();

        float s0 = 0.f, s1 = 0.f;
#pragma unroll
        for (int i = 0; i < 64; i += 4) {
            float p0 = 1.f / (1.f + __expf(-5.f * (aS[i]     - m0)));
            float p1 = 1.f / (1.f + __expf(-5.f * (aS[i + 1] - m0)));
            float p2 = 1.f / (1.f + __expf(-5.f * (aS[i + 2] - m1)));
            float p3 = 1.f / (1.f + __expf(-5.f * (aS[i + 3] - m1)));
            aS[i] = p0; aS[i + 1] = p1; aS[i + 2] = p2; aS[i + 3] = p3;
            s0 += p0 + p1; s1 += p2 + p3;
        }
        s0 += __shfl_xor_sync(0xFFFFFFFFu, s0, 1);
        s0 += __shfl_xor_sync(0xFFFFFFFFu, s0, 2);
        s1 += __shfl_xor_sync(0xFFFFFFFFu, s1, 1);
        s1 += __shfl_xor_sync(0xFFFFFFFFu, s1, 2);
        if (t == 0) {
            stats[(wm + g) * 4 + wni] = s0;
            stats[(wm + 8 + g) * 4 + wni] = s1;
        }
        __syncthreads();
        {
            float4 v0 = *(float4*)&stats[(wm + g) * 4];
            s0 = v0.x + v0.y + v0.z + v0.w;
            float4 v1 = *(float4*)&stats[(wm + 8 + g) * 4];
            s1 = v1.x + v1.y + v1.z + v1.w;
        }
        const float inv0 = 1.f / (s0 + 1e-8f);
        const float inv1 = 1.f / (s1 + 1e-8f);
#pragma unroll
        for (int i = 0; i < 64; i += 4) {
            aS[i]     = __uint_as_float(f2tf(aS[i]     * inv0));
            aS[i + 1] = __uint_as_float(f2tf(aS[i + 1] * inv0));
            aS[i + 2] = __uint_as_float(f2tf(aS[i + 2] * inv1));
            aS[i + 3] = __uint_as_float(f2tf(aS[i + 3] * inv1));
        }
    }

    // ---- phase 2: partial O (3-stage, 1 barrier/chunk) ----
    float acc2[8][4] = {};
#pragma unroll
    for (int c = 0; c < 8; c++) {
        if (c < 7) cpa_wait1(); else cpa_wait0();
        __syncthreads();
        if (c + 2 < 8) issueV(c + 2, (c + 2) % 3);
        const uint32_t* Vb = Vs + (c % 3) * FA_VBUF;
#pragma unroll
        for (int kt = 0; kt < 2; kt++) {
            uint32_t a[4];
            a[0] = __float_as_uint(accS[c][kt][0]);
            a[1] = __float_as_uint(accS[c][kt][2]);
            a[2] = __float_as_uint(accS[c][kt][1]);
            a[3] = __float_as_uint(accS[c][kt][3]);
            const int klb = wn + kt * 8 + t;
#pragma unroll
            for (int ci = 0; ci < 8; ci++) {
                const int n = ci * 8 + g;
                uint32_t b0 = Vb[klb * FA_V_W + n];
                uint32_t b1 = Vb[(klb + 4) * FA_V_W + n];
                mma8(acc2[ci], a, b0, b1);
            }
        }
    }

    // ---- epilogue: store partials (Opart overlays dead Q+K), reduce, STG ----
    {
        const int opb = warp * 1088;
#pragma unroll
        for (int ci = 0; ci < 8; ci++) {
            float2 v0 = {acc2[ci][0], acc2[ci][1]};
            *(float2*)&Opart[opb + g * FA_QK_W + ci * 8 + 2 * t] = v0;
            float2 v1 = {acc2[ci][2], acc2[ci][3]};
            *(float2*)&Opart[opb + (g + 8) * FA_QK_W + ci * 8 + 2 * t] = v1;
        }
    }
    __syncthreads();
    {
        const int rr = tid >> 3;
        const int c8 = (tid & 7) * 8;
        float4 o0 = {0.f, 0.f, 0.f, 0.f}, o1 = {0.f, 0.f, 0.f, 0.f};
#pragma unroll
        for (int wv = 0; wv < 4; wv++) {
            const float* src = Opart + ((rr >> 4) * 4 + wv) * 1088
                             + (rr & 15) * FA_QK_W + c8;
            float4 x0 = *(const float4*)src;
            float4 x1 = *(const float4*)(src + 4);
            o0.x += x0.x; o0.y += x0.y; o0.z += x0.z; o0.w += x0.w;
            o1.x += x1.x; o1.y += x1.y; o1.z += x1.z; o1.w += x1.w;
        }
        *(float4*)(Cg + (size_t)rr * 512 + c8) = o0;
        *(float4*)(Cg + (size_t)rr * 512 + c8 + 4) = o1;
    }
}

// ============================================================================
// launch
// ============================================================================
extern "C" void kernel_launch(void* const* d_in, const int* in_sizes, int n_in,
                              void* d_out, int out_size)
{
    const float* q_sp = (const float*)d_in[0];
    const float* k_sp = (const float*)d_in[1];
    const float* v_sp = (const float*)d_in[2];
    const float* Wq = (const float*)d_in[3];  const float* bq = (const float*)d_in[4];
    const float* Wk = (const float*)d_in[5];  const float* bk = (const float*)d_in[6];
    const float* Wv = (const float*)d_in[7];  const float* bv = (const float*)d_in[8];
    const float* Wo = (const float*)d_in[9];  const float* bo = (const float*)d_in[10];
    const float* mw    = (const float*)d_in[11];
    const float* tsync = (const float*)d_in[12];
    const int* qm = (const int*)d_in[13];
    const int* km = (const int*)d_in[14];
    float* out = (float*)d_out;

    // unconditional (no static guards): idempotent, not stream-ordered
    cudaFuncSetAttribute(proj3_gemm, cudaFuncAttributeMaxDynamicSharedMemorySize, PJ_SMEM);
    cudaFuncSetAttribute(fused_attn, cudaFuncAttributeMaxDynamicSharedMemorySize, FA_SMEM);

    float *dQ, *dK, *dV, *dAtt;
    cudaGetSymbolAddress((void**)&dQ, g_Q);
    cudaGetSymbolAddress((void**)&dK, g_K);
    cudaGetSymbolAddress((void**)&dV, g_V);
    cudaGetSymbolAddress((void**)&dAtt, g_att);

    // Q, K, V projections in one launch (outputs tf32-rounded for fused_attn)
    proj3_gemm<<<dim3(D_EMB / 128, M_ROWS / 128, 3), 256, PJ_SMEM>>>(
        q_sp, Wq, bq, dQ,
        k_sp, Wk, bk, dK,
        v_sp, Wv, bv, dV, 1);

    fused_attn<<<dim3(SEQ / 64, PBATCH), 512, FA_SMEM>>>(mw, tsync, qm, km);

    // output projection (full fp32 output)
    proj3_gemm<<<dim3(D_EMB / 128, M_ROWS / 128, 1), 256, PJ_SMEM>>>(
        dAtt, Wo, bo, out,
        dAtt, Wo, bo, out,
        dAtt, Wo, bo, out, 0);
}